// round 15
// baseline (speedup 1.0000x reference)
#include <cuda_runtime.h>
#include <cuda_bf16.h>
#include <cuda_fp16.h>
#include <cstdint>

#define Eg 16384
#define Ng 4096
#define Dg 128
#define DD 16384

static __device__ float g_x1[Eg*256];
static __device__ float g_x2[Eg*256];
static __device__ float g_x3[Eg*Dg];          // RAW (pre-BN) layer-3 output
static __device__ float g_C3[Dg*Dg];
static __device__ float g_ps1[256], g_pq1[256];
static __device__ float g_ps2[256], g_pq2[256];
static __device__ float g_ps3[128], g_pq3[128];
static __device__ float g_mx3sum[128];
static __device__ float g_msgsum[Ng*Dg];
static __device__ float g_S[Ng*Dg];
static __device__ float g_cnt[Ng];
static __device__ float g_mrelu[Ng*Dg];
static __device__ float g_gi[Ng*384];
static __device__ float g_gh[Ng*384];
static __device__ unsigned short g_Gh[DD*128];
static __device__ unsigned short g_W1h[4096],   g_W1l[4096];
static __device__ unsigned short g_W2h[65536],  g_W2l[65536];
static __device__ unsigned short g_W3h[32768],  g_W3l[32768];
static __device__ unsigned short g_Wihh[49152], g_Wihl[49152];
static __device__ unsigned short g_Whhh[49152], g_Whhl[49152];
static __device__ unsigned short g_C3h[16384],  g_C3l[16384];
static __device__ unsigned short g_bTh[16384],  g_bTl[16384];

// ---------- helpers ----------
__device__ __forceinline__ uint32_t smem_u32(const void* p) {
    uint32_t a;
    asm("{ .reg .u64 t; cvta.to.shared.u64 t, %1; cvt.u32.u64 %0, t; }" : "=r"(a) : "l"(p));
    return a;
}
__device__ __forceinline__ void mma_bf16(float* d, const uint32_t* a, const uint32_t* b, const float* c) {
    asm volatile("mma.sync.aligned.m16n8k16.row.col.f32.bf16.bf16.f32 "
        "{%0,%1,%2,%3}, {%4,%5,%6,%7}, {%8,%9}, {%10,%11,%12,%13};"
        : "=f"(d[0]),"=f"(d[1]),"=f"(d[2]),"=f"(d[3])
        : "r"(a[0]),"r"(a[1]),"r"(a[2]),"r"(a[3]), "r"(b[0]),"r"(b[1]),
          "f"(c[0]),"f"(c[1]),"f"(c[2]),"f"(c[3]));
}
__device__ __forceinline__ void mma_f16(float* d, const uint32_t* a, const uint32_t* b, const float* c) {
    asm volatile("mma.sync.aligned.m16n8k16.row.col.f32.f16.f16.f32 "
        "{%0,%1,%2,%3}, {%4,%5,%6,%7}, {%8,%9}, {%10,%11,%12,%13};"
        : "=f"(d[0]),"=f"(d[1]),"=f"(d[2]),"=f"(d[3])
        : "r"(a[0]),"r"(a[1]),"r"(a[2]),"r"(a[3]), "r"(b[0]),"r"(b[1]),
          "f"(c[0]),"f"(c[1]),"f"(c[2]),"f"(c[3]));
}
__device__ __forceinline__ void ldsm4(uint32_t* r, uint32_t addr) {
    asm volatile("ldmatrix.sync.aligned.m8n8.x4.shared.b16 {%0,%1,%2,%3}, [%4];"
        : "=r"(r[0]),"=r"(r[1]),"=r"(r[2]),"=r"(r[3]) : "r"(addr));
}
__device__ __forceinline__ void cp16(uint32_t dst, const void* src) {
    asm volatile("cp.async.cg.shared.global [%0], [%1], 16;" :: "r"(dst), "l"(src));
}
#define CP_COMMIT() asm volatile("cp.async.commit_group;" ::: "memory")
__device__ __forceinline__ uint32_t f2h2(float2 p) {
    __half2 h = __float22half2_rn(p);
    return *(uint32_t*)&h;
}
__device__ __forceinline__ void split2(float2 p, uint32_t& hi, uint32_t& lo) {
    uint32_t u0=__float_as_uint(p.x), u1=__float_as_uint(p.y);
    hi = __byte_perm(u0,u1,0x7632);
    float h0=__uint_as_float(u0&0xFFFF0000u), h1=__uint_as_float(u1&0xFFFF0000u);
    __nv_bfloat162 l2=__floats2bfloat162_rn(p.x-h0,p.y-h1);
    lo = *(uint32_t*)&l2;
}

// ---------- fused init ----------
__global__ void init_kernel(const float* W1, const float* W2, const float* W3,
                            const float* Wih, const float* Whh)
{
    int i = blockIdx.x*256 + threadIdx.x;
    if (i < Ng*Dg) { g_msgsum[i]=0.f; g_S[i]=0.f; }
    if (i < Ng)    g_cnt[i]=0.f;
    if (i < Dg*Dg) g_C3[i]=0.f;
    if (i < 256)   { g_ps1[i]=0.f; g_pq1[i]=0.f; g_ps2[i]=0.f; g_pq2[i]=0.f; }
    if (i < 128)   { g_ps3[i]=0.f; g_pq3[i]=0.f; g_mx3sum[i]=0.f; }
    if (i < 200704) {
        const float* src; unsigned short *dh, *dl; int off;
        if (i < 4096)        { src=W1;  dh=g_W1h;  dl=g_W1l;  off=i; }
        else if (i < 69632)  { src=W2;  dh=g_W2h;  dl=g_W2l;  off=i-4096; }
        else if (i < 102400) { src=W3;  dh=g_W3h;  dl=g_W3l;  off=i-69632; }
        else if (i < 151552) { src=Wih; dh=g_Wihh; dl=g_Wihl; off=i-102400; }
        else                 { src=Whh; dh=g_Whhh; dl=g_Whhl; off=i-151552; }
        float v = src[off];
        uint32_t u = __float_as_uint(v);
        dh[off] = (unsigned short)(u>>16);
        __nv_bfloat16 lb = __float2bfloat16_rn(v - __uint_as_float(u & 0xFFFF0000u));
        dl[off] = *(unsigned short*)&lb;
    }
}
__global__ void csplit_kernel()
{
    int i = blockIdx.x*256 + threadIdx.x;
    float v = g_C3[i];
    uint32_t u = __float_as_uint(v);
    g_C3h[i] = (unsigned short)(u>>16);
    __nv_bfloat16 lb = __float2bfloat16_rn(v - __uint_as_float(u & 0xFFFF0000u));
    g_C3l[i] = *(unsigned short*)&lb;
}
__global__ void ssum_kernel(const int* __restrict__ ei, const float* __restrict__ node)
{
    int idx = blockIdx.x*256 + threadIdx.x;
    if (idx >= Eg*128) return;
    int e = idx>>7, k = idx&127;
    int dst = ei[2*e+1];
    atomicAdd(&g_S[(size_t)dst*128 + k], node[(size_t)ei[2*e]*128 + k]);
    if (k == 0) atomicAdd(&g_cnt[dst], 1.0f);
}

// ---------- unified tensor-core GEMM (cooperative A conversion) ----------
#define SA_OFF(s)  ((s)*10240)
#define SBH_OFF(s) (20480 + (s)*12288)
#define SBL_OFF(s) (20480 + (s)*12288 + 6144)
#define SAH_OFF(s) (45056 + (s)*12288)
#define SAL_OFF(s) (45056 + (s)*12288 + 6144)
#define SSC_OFF    69632
#define SSH_OFF    70656
#define H_SMEM     71680

__global__ __launch_bounds__(256) void hgemm(
    const float* A,
    const unsigned short* Bh, const unsigned short* Bl,
    float* C, const float* bias,
    int M, int Nc, int K,
    int amode, const float* __restrict__ psA, const float* __restrict__ pqA,
    const float* __restrict__ gA, const float* __restrict__ bA, float invE,
    int emode, float* __restrict__ psO, float* __restrict__ pqO,
    const float* A2, const unsigned short* Bh2, const unsigned short* Bl2,
    float* C2, const float* bias2)
{
    if (blockIdx.z) { A=A2; Bh=Bh2; Bl=Bl2; C=C2; bias=bias2; }
    extern __shared__ char sm[];
    uint32_t smb = smem_u32(sm);
    float* sScale = (float*)(sm + SSC_OFF);
    float* sShift = (float*)(sm + SSH_OFF);
    int tid = threadIdx.x, l = tid&31, wid = tid>>5;
    int m0 = blockIdx.y*128, n0 = blockIdx.x*128;
    int wm = (wid>>1)*32, wn = (wid&1)*64;
    int r = l>>2, c2 = (l&3)*2;
    int ln = ((l>>4)&1)*8 + (l&7);
    int colsel = (l>>3)&1;
    uint32_t aoff = (uint32_t)((l&7) + ((l>>3)&1)*8)*48 + ((l>>4)&1)*16;

    if (amode) {
        for (int c = tid; c < K; c += 256) {
            float m = psA[c]*invE;
            float var = pqA[c]*invE - m*m;
            float sc = rsqrtf(var + 1e-5f) * gA[c];
            sScale[c] = sc;
            sShift[c] = bA[c] - m*sc;
        }
    }

    float acc[2][8][4];
    #pragma unroll
    for (int mf=0;mf<2;++mf)
        #pragma unroll
        for (int nf=0;nf<8;++nf) { acc[mf][nf][0]=0;acc[mf][nf][1]=0;acc[mf][nf][2]=0;acc[mf][nf][3]=0; }

    int steps = K>>4;
    {
        #pragma unroll
        for (int i=0;i<2;++i) {
            int q = tid + i*256, row = q>>2, c4 = q&3;
            cp16(smb + SA_OFF(0) + row*80 + c4*16, A + (size_t)(m0+row)*K + c4*4);
        }
        int row = tid>>1, c = tid&1;
        cp16(smb + SBH_OFF(0) + row*48 + c*16, Bh + (size_t)(n0+row)*K + c*8);
        cp16(smb + SBL_OFF(0) + row*48 + c*16, Bl + (size_t)(n0+row)*K + c*8);
        CP_COMMIT();
    }

    for (int s=0; s<steps; ++s) {
        if (s+1 < steps) {
            int b = (s+1)&1, k0 = (s+1)*16;
            #pragma unroll
            for (int i=0;i<2;++i) {
                int q = tid + i*256, row = q>>2, c4 = q&3;
                cp16(smb + SA_OFF(b) + row*80 + c4*16, A + (size_t)(m0+row)*K + k0 + c4*4);
            }
            int row = tid>>1, c = tid&1;
            cp16(smb + SBH_OFF(b) + row*48 + c*16, Bh + (size_t)(n0+row)*K + k0 + c*8);
            cp16(smb + SBL_OFF(b) + row*48 + c*16, Bl + (size_t)(n0+row)*K + k0 + c*8);
            CP_COMMIT();
            asm volatile("cp.async.wait_group 1;" ::: "memory");
        } else {
            asm volatile("cp.async.wait_group 0;" ::: "memory");
        }
        __syncthreads();

        int k0 = s*16;
        {
            int row = tid>>1, hf = tid&1;
            const float* ar = (const float*)(sm + SA_OFF(s&1)) + row*20 + hf*8;
            float2 p[4];
            p[0]=*(const float2*)&ar[0]; p[1]=*(const float2*)&ar[2];
            p[2]=*(const float2*)&ar[4]; p[3]=*(const float2*)&ar[6];
            if (amode) {
                int cb = k0 + hf*8;
                #pragma unroll
                for (int q=0;q<4;++q) {
                    p[q].x = fmaxf(p[q].x*sScale[cb+2*q]   + sShift[cb+2*q],   0.f);
                    p[q].y = fmaxf(p[q].y*sScale[cb+2*q+1] + sShift[cb+2*q+1], 0.f);
                }
            }
            uint32_t hi[4], lo[4];
            #pragma unroll
            for (int q=0;q<4;++q) split2(p[q], hi[q], lo[q]);
            *(uint4*)(sm + SAH_OFF(s&1) + row*48 + hf*16) = make_uint4(hi[0],hi[1],hi[2],hi[3]);
            *(uint4*)(sm + SAL_OFF(s&1) + row*48 + hf*16) = make_uint4(lo[0],lo[1],lo[2],lo[3]);
        }
        __syncthreads();

        uint32_t Ah[2][4], Al[2][4];
        #pragma unroll
        for (int mf=0;mf<2;++mf) {
            ldsm4(Ah[mf], smb + SAH_OFF(s&1) + (uint32_t)(wm+mf*16)*48 + aoff);
            ldsm4(Al[mf], smb + SAL_OFF(s&1) + (uint32_t)(wm+mf*16)*48 + aoff);
        }
        uint32_t bh4[4][4], bl4[4][4];
        #pragma unroll
        for (int i=0;i<4;++i) {
            uint32_t boff = (uint32_t)(wn + 16*i + ln)*48 + colsel*16;
            ldsm4(bh4[i], smb + SBH_OFF(s&1) + boff);
            ldsm4(bl4[i], smb + SBL_OFF(s&1) + boff);
        }

        #pragma unroll
        for (int mf=0;mf<2;++mf)
            #pragma unroll
            for (int nf=0;nf<8;++nf) {
                const uint32_t* bh = &bh4[nf>>1][(nf&1)*2];
                const uint32_t* bl = &bl4[nf>>1][(nf&1)*2];
                mma_bf16(acc[mf][nf], Ah[mf], bh, acc[mf][nf]);
                mma_bf16(acc[mf][nf], Al[mf], bh, acc[mf][nf]);
                mma_bf16(acc[mf][nf], Ah[mf], bl, acc[mf][nf]);
            }
    }

    if (emode == 2) {
        #pragma unroll
        for (int mf=0;mf<2;++mf) {
            int row0 = m0+wm+mf*16+r;
            float cn0 = fmaxf(g_cnt[row0],1.f), cn1 = fmaxf(g_cnt[row0+8],1.f);
            #pragma unroll
            for (int nf=0;nf<8;++nf) {
                int col = n0+wn+nf*8+c2;
                float2 bv = *(const float2*)&bias[col];
                float2 m0v = *(const float2*)&g_msgsum[(size_t)row0*Nc + col];
                float2 m1v = *(const float2*)&g_msgsum[(size_t)(row0+8)*Nc + col];
                float2 o0, o1;
                o0.x = fmaxf((acc[mf][nf][0]+m0v.x)/cn0 + bv.x, 0.f);
                o0.y = fmaxf((acc[mf][nf][1]+m0v.y)/cn0 + bv.y, 0.f);
                o1.x = fmaxf((acc[mf][nf][2]+m1v.x)/cn1 + bv.x, 0.f);
                o1.y = fmaxf((acc[mf][nf][3]+m1v.y)/cn1 + bv.y, 0.f);
                *(float2*)&C[(size_t)row0*Nc + col]     = o0;
                *(float2*)&C[(size_t)(row0+8)*Nc + col] = o1;
            }
        }
        return;
    }
    #pragma unroll
    for (int mf=0;mf<2;++mf) {
        int row0 = m0+wm+mf*16+r;
        #pragma unroll
        for (int nf=0;nf<8;++nf) {
            int col = n0+wn+nf*8+c2;
            float2 o0 = make_float2(acc[mf][nf][0], acc[mf][nf][1]);
            float2 o1 = make_float2(acc[mf][nf][2], acc[mf][nf][3]);
            if (bias) {
                float2 bv = *(const float2*)&bias[col];
                o0.x+=bv.x; o0.y+=bv.y; o1.x+=bv.x; o1.y+=bv.y;
            }
            *(float2*)&C[(size_t)row0*Nc + col]     = o0;
            *(float2*)&C[(size_t)(row0+8)*Nc + col] = o1;
        }
    }
    if (emode == 1) {
        #pragma unroll
        for (int nf=0;nf<8;++nf) {
            float s0=0,s1=0,q0=0,q1=0;
            #pragma unroll
            for (int mf=0;mf<2;++mf) {
                float a0=acc[mf][nf][0], a1=acc[mf][nf][1], a2=acc[mf][nf][2], a3=acc[mf][nf][3];
                s0+=a0+a2; s1+=a1+a3; q0+=a0*a0+a2*a2; q1+=a1*a1+a3*a3;
            }
            #pragma unroll
            for (int st=4; st<32; st<<=1) {
                s0 += __shfl_xor_sync(0xFFFFFFFF, s0, st);
                s1 += __shfl_xor_sync(0xFFFFFFFF, s1, st);
                q0 += __shfl_xor_sync(0xFFFFFFFF, q0, st);
                q1 += __shfl_xor_sync(0xFFFFFFFF, q1, st);
            }
            if (l < 4) {
                int col = n0+wn+nf*8+c2;
                atomicAdd(&psO[col], s0);   atomicAdd(&psO[col+1], s1);
                atomicAdd(&pqO[col], q0);   atomicAdd(&pqO[col+1], q1);
            }
        }
    }
}

// ---------- fused W4 stage ----------
#define W4A(s)   ((s)*10240)
#define W4BH     20480
#define W4BL     (20480+34816)
#define W4STASH  (20480+2*34816)
#define W4_SMEM  (W4STASH + 128*132*4)

__global__ __launch_bounds__(256,1) void w4fuse_kernel(
    const float* __restrict__ W4, const float* __restrict__ g4, const float* __restrict__ b4)
{
    extern __shared__ char sm[];
    uint32_t smb = smem_u32(sm);
    float* stash = (float*)(sm + W4STASH);
    __shared__ float sQ[128][2], sMs[128][2], sAlpha[128], sMx[128];
    int tid = threadIdx.x, l = tid&31, wid = tid>>5;
    int m0 = blockIdx.x*128;
    int wm = (wid>>1)*32, wn = (wid&1)*64;
    int r = l>>2, c2 = (l&3)*2;
    int ln = ((l>>4)&1)*8 + (l&7);
    int colsel = (l>>3)&1;

    if (tid < 128) sMx[tid] = g_mx3sum[tid];

    {
        const char* BH = (const char*)g_C3h;
        const char* BL = (const char*)g_C3l;
        #pragma unroll
        for (int i=0;i<8;++i) {
            int q = tid + i*256;
            int row = q>>4, c16 = q&15;
            cp16(smb + W4BH + row*272 + c16*16, BH + row*256 + c16*16);
            cp16(smb + W4BL + row*272 + c16*16, BL + row*256 + c16*16);
        }
        #pragma unroll
        for (int i=0;i<2;++i) {
            int q = tid + i*256, row = q>>2, c4 = q&3;
            cp16(smb + W4A(0) + row*80 + c4*16, W4 + (size_t)(m0+row)*128 + c4*4);
        }
        CP_COMMIT();
    }

    float acc[2][8][4];
    #pragma unroll
    for (int mf=0;mf<2;++mf)
        #pragma unroll
        for (int nf=0;nf<8;++nf) { acc[mf][nf][0]=0;acc[mf][nf][1]=0;acc[mf][nf][2]=0;acc[mf][nf][3]=0; }

    for (int s=0; s<8; ++s) {
        if (s+1 < 8) {
            int b = (s+1)&1, k0 = (s+1)*16;
            #pragma unroll
            for (int i=0;i<2;++i) {
                int q = tid + i*256, row = q>>2, c4 = q&3;
                cp16(smb + W4A(b) + row*80 + c4*16, W4 + (size_t)(m0+row)*128 + k0 + c4*4);
            }
            CP_COMMIT();
            asm volatile("cp.async.wait_group 1;" ::: "memory");
        } else {
            asm volatile("cp.async.wait_group 0;" ::: "memory");
        }
        __syncthreads();

        #pragma unroll
        for (int i=0;i<2;++i) {
            int q = tid + i*256, row = q>>2, c4 = q&3;
            float4 v = *(const float4*)(sm + W4A(s&1) + row*80 + c4*16);
            *(float4*)&stash[row*132 + s*16 + c4*4] = v;
        }

        const float* a_ = (const float*)(sm + W4A(s&1));
        uint32_t Ah[2][4], Al[2][4];
        #pragma unroll
        for (int mf=0;mf<2;++mf) {
            const float* r0 = a_ + (wm+mf*16+r)*20;
            const float* r1 = a_ + (wm+mf*16+r+8)*20;
            float2 p[4];
            p[0]=*(const float2*)&r0[c2];   p[1]=*(const float2*)&r1[c2];
            p[2]=*(const float2*)&r0[c2+8]; p[3]=*(const float2*)&r1[c2+8];
            #pragma unroll
            for (int q=0;q<4;++q) split2(p[q], Ah[mf][q], Al[mf][q]);
        }
        uint32_t bh4[4][4], bl4[4][4];
        #pragma unroll
        for (int i=0;i<4;++i) {
            uint32_t boff = (uint32_t)(wn + 16*i + ln)*272 + s*32 + colsel*16;
            ldsm4(bh4[i], smb + W4BH + boff);
            ldsm4(bl4[i], smb + W4BL + boff);
        }
        __syncthreads();

        #pragma unroll
        for (int mf=0;mf<2;++mf)
            #pragma unroll
            for (int nf=0;nf<8;++nf) {
                const uint32_t* bh = &bh4[nf>>1][(nf&1)*2];
                const uint32_t* bl = &bl4[nf>>1][(nf&1)*2];
                mma_bf16(acc[mf][nf], Ah[mf], bh, acc[mf][nf]);
                mma_bf16(acc[mf][nf], Al[mf], bh, acc[mf][nf]);
                mma_bf16(acc[mf][nf], Ah[mf], bl, acc[mf][nf]);
            }
    }

    float qv[2][2]={{0,0},{0,0}}, mv[2][2]={{0,0},{0,0}};
    #pragma unroll
    for (int mf=0;mf<2;++mf) {
        int r0 = wm+mf*16+r;
        #pragma unroll
        for (int nf=0;nf<8;++nf) {
            int col = wn+nf*8+c2;
            float2 w0 = *(const float2*)&stash[r0*132 + col];
            float2 w1 = *(const float2*)&stash[(r0+8)*132 + col];
            float mx0 = sMx[col], mx1 = sMx[col+1];
            qv[mf][0] += acc[mf][nf][0]*w0.x + acc[mf][nf][1]*w0.y;
            mv[mf][0] += w0.x*mx0 + w0.y*mx1;
            qv[mf][1] += acc[mf][nf][2]*w1.x + acc[mf][nf][3]*w1.y;
            mv[mf][1] += w1.x*mx0 + w1.y*mx1;
        }
    }
    #pragma unroll
    for (int mf=0;mf<2;++mf)
        #pragma unroll
        for (int h=0;h<2;++h) {
            float q = qv[mf][h], m = mv[mf][h];
            q += __shfl_xor_sync(0xFFFFFFFF, q, 1);
            q += __shfl_xor_sync(0xFFFFFFFF, q, 2);
            m += __shfl_xor_sync(0xFFFFFFFF, m, 1);
            m += __shfl_xor_sync(0xFFFFFFFF, m, 2);
            if ((l&3) == 0) {
                int row = wm+mf*16+r+h*8;
                sQ[row][wid&1]  = q;
                sMs[row][wid&1] = m;
            }
        }
    __syncthreads();
    if (tid < 128) {
        float q  = sQ[tid][0]  + sQ[tid][1];
        float ms = sMs[tid][0] + sMs[tid][1];
        int c = m0 + tid;
        float m4 = ms*(1.f/Eg);
        float var = q*(1.f/Eg) - m4*m4;
        float a = g4[c]*rsqrtf(var + 1e-5f);
        sAlpha[tid] = a;
        float bv = b4[c] - m4*a;
        int t = (c&127)*128 + (c>>7);
        uint32_t uu = __float_as_uint(bv);
        g_bTh[t] = (unsigned short)(uu>>16);
        __nv_bfloat16 lb = __float2bfloat16_rn(bv - __uint_as_float(uu & 0xFFFF0000u));
        g_bTl[t] = *(unsigned short*)&lb;
    }
    __syncthreads();
    {
        int row = tid>>1, hf = tid&1;
        float a = sAlpha[row];
        unsigned short* dst = g_Gh + (size_t)(m0+row)*128 + hf*64;
        const float* src = &stash[row*132 + hf*64];
        #pragma unroll
        for (int i=0;i<8;++i) {
            float2 p0 = *(const float2*)&src[i*8+0];
            float2 p1 = *(const float2*)&src[i*8+2];
            float2 p2 = *(const float2*)&src[i*8+4];
            float2 p3 = *(const float2*)&src[i*8+6];
            p0.x*=a; p0.y*=a; p1.x*=a; p1.y*=a;
            p2.x*=a; p2.y*=a; p3.x*=a; p3.y*=a;
            uint4 o;
            o.x = f2h2(p0); o.y = f2h2(p1); o.z = f2h2(p2); o.w = f2h2(p3);
            *(uint4*)(dst + i*8) = o;
        }
    }
}

// ---------- SYRK on BN'd x3 + column sums ----------
__global__ __launch_bounds__(256) void syrk_x3(const float* __restrict__ g3,
                                               const float* __restrict__ b3)
{
    __shared__ float sAcc[8][1024];
    __shared__ float sSc[128], sSh[128];
    int tid = threadIdx.x, lane = tid&31, w = tid>>5;
    if (tid < 128) {
        float m = g_ps3[tid]*(1.f/Eg);
        float var = g_pq3[tid]*(1.f/Eg) - m*m;
        float sc = rsqrtf(var+1e-5f)*g3[tid];
        sSc[tid] = sc;
        sSh[tid] = b3[tid] - m*sc;
    }
    __syncthreads();
    int i0 = blockIdx.x*8;
    int seg = Eg/gridDim.y, e0 = blockIdx.y*seg, e1 = e0+seg;
    float acc[8][4];
    #pragma unroll
    for (int a=0;a<8;++a){acc[a][0]=0;acc[a][1]=0;acc[a][2]=0;acc[a][3]=0;}
    float csum[4]={0,0,0,0};
    float scv[4], shv[4], sci[8], shi[8];
    #pragma unroll
    for (int b=0;b<4;++b){ scv[b]=sSc[lane*4+b]; shv[b]=sSh[lane*4+b]; }
    #pragma unroll
    for (int a=0;a<8;++a){ sci[a]=sSc[i0+a]; shi[a]=sSh[i0+a]; }
    bool do_csum = (blockIdx.x == 0);

    for (int e=e0+w; e<e1; e+=8) {
        const float* row = g_x3 + (size_t)e*128;
        float4 xj = *(const float4*)&row[lane*4];
        float4 x0 = *(const float4*)&row[i0];
        float4 x1 = *(const float4*)&row[i0+4];
        float xr[8]={x0.x,x0.y,x0.z,x0.w,x1.x,x1.y,x1.z,x1.w};
        float xi[8], xv[4];
        xv[0]=fmaxf(xj.x*scv[0]+shv[0],0.f); xv[1]=fmaxf(xj.y*scv[1]+shv[1],0.f);
        xv[2]=fmaxf(xj.z*scv[2]+shv[2],0.f); xv[3]=fmaxf(xj.w*scv[3]+shv[3],0.f);
        #pragma unroll
        for (int a=0;a<8;++a) xi[a]=fmaxf(xr[a]*sci[a]+shi[a],0.f);
        if (do_csum) { csum[0]+=xv[0]; csum[1]+=xv[1]; csum[2]+=xv[2]; csum[3]+=xv[3]; }
        #pragma unroll
        for (int a=0;a<8;++a)
            #pragma unroll
            for (int b=0;b<4;++b) acc[a][b]+=xi[a]*xv[b];
    }
    #pragma unroll
    for (int a=0;a<8;++a)
        *(float4*)&sAcc[w][a*128+lane*4]=make_float4(acc[a][0],acc[a][1],acc[a][2],acc[a][3]);
    __syncthreads();
    for (int o=tid;o<1024;o+=256) {
        float s=0.f;
        #pragma unroll
        for (int ww=0;ww<8;++ww) s+=sAcc[ww][o];
        atomicAdd(&g_C3[(i0+(o>>7))*128 + (o&127)], s);
    }
    if (do_csum) {
        #pragma unroll
        for (int b=0;b<4;++b) atomicAdd(&g_mx3sum[lane*4+b], csum[b]);
    }
}

// ---------- big fused GEMM: 128-edge tiles, e×k warp split, 4-buf 3-deep pipeline ----------
#define ROWB   272
#define BUF_SIZE  (128*ROWB)
#define XIT_OFF   (4*BUF_SIZE)
#define BIG_SMEM  (XIT_OFF + 65536)

__device__ __forceinline__ void load_G(int d, int tid, uint32_t smem_base) {
    const char* GH = (const char*)g_Gh;
    uint32_t bufb = smem_base + (d&3)*BUF_SIZE;
    #pragma unroll
    for (int i=0;i<8;++i) {
        int q = tid + i*256;
        int row = q>>4, c16 = q&15;
        cp16(bufb + row*ROWB + c16*16, GH + ((size_t)d*128 + row)*256 + c16*16);
    }
    CP_COMMIT();
}

__global__ __launch_bounds__(256,1) void big_msg_kernel(
    const float* __restrict__ node, const int* __restrict__ ei,
    const float* __restrict__ g3, const float* __restrict__ b3)
{
    extern __shared__ char sm[];
    float* xiT = (float*)(sm + XIT_OFF);
    __shared__ int sDst[128];
    __shared__ float sSc3[128], sSh3[128];
    int tid = threadIdx.x, l = tid&31, w = tid>>5;
    int e0 = blockIdx.x*128;
    if (tid < 128) {
        float m = g_ps3[tid]*(1.f/Eg);
        float var = g_pq3[tid]*(1.f/Eg) - m*m;
        float sc = rsqrtf(var+1e-5f)*g3[tid];
        sSc3[tid] = sc;
        sSh3[tid] = b3[tid] - m*sc;
    }
    {
        int e = tid>>1, hf = tid&1;
        int src = ei[2*(e0+e)];
        if (hf==0) sDst[e] = ei[2*(e0+e)+1];
        const float* nr = node + (size_t)src*128 + hf*64;
        #pragma unroll
        for (int i=0;i<16;++i) {
            float4 v = *(const float4*)&nr[i*4];
            int d = hf*64 + i*4;
            xiT[(d+0)*128+e]=v.x; xiT[(d+1)*128+e]=v.y; xiT[(d+2)*128+e]=v.z; xiT[(d+3)*128+e]=v.w;
        }
    }
    float* sx3 = (float*)sm;
    {
        const float* xr = g_x3 + (size_t)e0*128;
        #pragma unroll
        for (int i=0;i<16;++i) {
            int u = tid + i*256;
            *(float4*)&sx3[u*4] = *(const float4*)&xr[u*4];
        }
    }
    __syncthreads();

    int ew = (w&3)*32, kh = w>>2;
    int r = l>>2, cq = (l&3)*2;
    uint32_t Af[8][2][4];
    {
        #pragma unroll
        for (int mf=0;mf<2;++mf) {
            const float* Xr0 = sx3 + (size_t)(ew + mf*16 + r)*128;
            const float* Xr1 = sx3 + (size_t)(ew + mf*16 + r + 8)*128;
            #pragma unroll
            for (int jt=0;jt<8;++jt) {
                int c0 = jt*16 + cq;
                float sa=sSc3[c0],   ha=sSh3[c0];
                float sb=sSc3[c0+1], hb=sSh3[c0+1];
                float sc=sSc3[c0+8], hc=sSh3[c0+8];
                float sd=sSc3[c0+9], hd=sSh3[c0+9];
                float2 p0=*(const float2*)&Xr0[c0],   p1=*(const float2*)&Xr1[c0];
                float2 p2=*(const float2*)&Xr0[c0+8], p3=*(const float2*)&Xr1[c0+8];
                p0.x=fmaxf(p0.x*sa+ha,0.f); p0.y=fmaxf(p0.y*sb+hb,0.f);
                p1.x=fmaxf(p1.x*sa+ha,0.f); p1.y=fmaxf(p1.y*sb+hb,0.f);
                p2.x=fmaxf(p2.x*sc+hc,0.f); p2.y=fmaxf(p2.y*sd+hd,0.f);
                p3.x=fmaxf(p3.x*sc+hc,0.f); p3.y=fmaxf(p3.y*sd+hd,0.f);
                Af[jt][mf][0]=f2h2(p0); Af[jt][mf][1]=f2h2(p1);
                Af[jt][mf][2]=f2h2(p2); Af[jt][mf][3]=f2h2(p3);
            }
        }
    }
    __syncthreads();

    uint32_t smem_base = smem_u32(sm);
    int ln = ((l>>4)&1)*8 + (l&7);
    int colsel = (l>>3)&1;
    uint32_t laneoff = (uint32_t)(kh*64 + ln)*ROWB + colsel*16;

    float msg[2][8][4];
    #pragma unroll
    for (int mf=0;mf<2;++mf)
        #pragma unroll
        for (int nt=0;nt<8;++nt) { msg[mf][nt][0]=0;msg[mf][nt][1]=0;msg[mf][nt][2]=0;msg[mf][nt][3]=0; }

    // persistent zero C-operand (never written)
    float zr[4];
    zr[0]=0.f; zr[1]=0.f; zr[2]=0.f; zr[3]=0.f;

    load_G(0, tid, smem_base);
    load_G(1, tid, smem_base);
    load_G(2, tid, smem_base);

    // xi prefetch registers (for d=0)
    float nxi00 = xiT[0*128 + ew + r];
    float nxi01 = xiT[0*128 + ew + r + 8];
    float nxi10 = xiT[0*128 + ew + 16 + r];
    float nxi11 = xiT[0*128 + ew + 16 + r + 8];

    for (int d = 0; d < 128; ++d) {
        if (d < 126)       asm volatile("cp.async.wait_group 2;" ::: "memory");
        else if (d == 126) asm volatile("cp.async.wait_group 1;" ::: "memory");
        else               asm volatile("cp.async.wait_group 0;" ::: "memory");
        __syncthreads();
        if (d <= 124) load_G(d+3, tid, smem_base);

        uint32_t aH = smem_base + (d&3)*BUF_SIZE + laneoff;
        float xi00 = nxi00, xi01 = nxi01, xi10 = nxi10, xi11 = nxi11;
        if (d < 127) {
            nxi00 = xiT[(d+1)*128 + ew + r];
            nxi01 = xiT[(d+1)*128 + ew + r + 8];
            nxi10 = xiT[(d+1)*128 + ew + 16 + r];
            nxi11 = xiT[(d+1)*128 + ew + 16 + r + 8];
        }

        #pragma unroll
        for (int ntp = 0; ntp < 4; ++ntp) {
            float v0[8], v1[8];
            uint32_t rowoff = (uint32_t)ntp*16*ROWB;
            // jt = 0: write vh via zero-C mma (no explicit zero-init MOVs)
            {
                uint32_t bh[4];
                ldsm4(bh, aH + rowoff);
                mma_f16(v0,   Af[0][0], bh,   zr);
                mma_f16(v0+4, Af[0][0], bh+2, zr);
                mma_f16(v1,   Af[0][1], bh,   zr);
                mma_f16(v1+4, Af[0][1], bh+2, zr);
            }
            #pragma unroll
            for (int jt = 1; jt < 8; ++jt) {
                uint32_t bh[4];
                ldsm4(bh, aH + rowoff + jt*32);
                mma_f16(v0,   Af[jt][0], bh,   v0);
                mma_f16(v0+4, Af[jt][0], bh+2, v0+4);
                mma_f16(v1,   Af[jt][1], bh,   v1);
                mma_f16(v1+4, Af[jt][1], bh+2, v1+4);
            }
            msg[0][2*ntp  ][0] += xi00*v0[0];
            msg[0][2*ntp  ][1] += xi00*v0[1];
            msg[0][2*ntp  ][2] += xi01*v0[2];
            msg[0][2*ntp  ][3] += xi01*v0[3];
            msg[0][2*ntp+1][0] += xi00*v0[4];
            msg[0][2*ntp+1][1] += xi00*v0[5];
            msg[0][2*ntp+1][2] += xi01*v0[6];
            msg[0][2*ntp+1][3] += xi01*v0[7];
            msg[1][2*ntp  ][0] += xi10*v1[0];
            msg[1][2*ntp  ][1] += xi10*v1[1];
            msg[1][2*ntp  ][2] += xi11*v1[2];
            msg[1][2*ntp  ][3] += xi11*v1[3];
            msg[1][2*ntp+1][0] += xi10*v1[4];
            msg[1][2*ntp+1][1] += xi10*v1[5];
            msg[1][2*ntp+1][2] += xi11*v1[6];
            msg[1][2*ntp+1][3] += xi11*v1[7];
        }
    }

    #pragma unroll
    for (int mf=0;mf<2;++mf) {
        int d0 = sDst[ew + mf*16 + r], d1 = sDst[ew + mf*16 + r + 8];
        #pragma unroll
        for (int nt = 0; nt < 8; ++nt) {
            int k = kh*64 + nt*8 + cq;
            atomicAdd(&g_msgsum[(size_t)d0*128 + k],     msg[mf][nt][0]);
            atomicAdd(&g_msgsum[(size_t)d0*128 + k + 1], msg[mf][nt][1]);
            atomicAdd(&g_msgsum[(size_t)d1*128 + k],     msg[mf][nt][2]);
            atomicAdd(&g_msgsum[(size_t)d1*128 + k + 1], msg[mf][nt][3]);
        }
    }
}

__global__ void gru_kernel(const float* __restrict__ h0, float* __restrict__ out, int twice)
{
    int i = blockIdx.x*256 + threadIdx.x;
    if (i >= Ng*Dg) return;
    int n = i>>7, k = i&127;
    const float* gir = g_gi + (size_t)n*384;
    const float* ghr = g_gh + (size_t)n*384;
    float r = 1.f/(1.f + expf(-(gir[k]     + ghr[k])));
    float z = 1.f/(1.f + expf(-(gir[128+k] + ghr[128+k])));
    float nn = tanhf(gir[256+k] + r*ghr[256+k]);
    float hn = (1.f - z)*nn + z*h0[i];
    out[i] = hn;
    if (twice) out[Ng*Dg + i] = hn;
}

static float* sym(const void* s) { void* p=0; cudaGetSymbolAddress(&p, s); return (float*)p; }
static unsigned short* symu(const void* s) { void* p=0; cudaGetSymbolAddress(&p, s); return (unsigned short*)p; }

extern "C" void kernel_launch(void* const* d_in, const int* in_sizes, int n_in,
                              void* d_out, int out_size)
{
    const float* node   = (const float*)d_in[0];
    const int*   ei     = (const int*)  d_in[1];
    const float* edge   = (const float*)d_in[2];
    const float* hidden = (const float*)d_in[3];
    const float* W1=(const float*)d_in[4],  *g1=(const float*)d_in[5],  *b1=(const float*)d_in[6];
    const float* W2=(const float*)d_in[7],  *g2=(const float*)d_in[8],  *b2=(const float*)d_in[9];
    const float* W3=(const float*)d_in[10], *g3=(const float*)d_in[11], *b3=(const float*)d_in[12];
    const float* W4=(const float*)d_in[13];
    const float* g4=(const float*)d_in[14], *b4=(const float*)d_in[15];
    const float* bias=(const float*)d_in[16];
    const float* W_ih=(const float*)d_in[17], *W_hh=(const float*)d_in[18];
    const float* b_ih=(const float*)d_in[19], *b_hh=(const float*)d_in[20];
    (void)in_sizes; (void)n_in;

    float *x1=sym(g_x1), *x2=sym(g_x2), *x3=sym(g_x3);
    float *ps1=sym(g_ps1), *pq1=sym(g_pq1), *ps2=sym(g_ps2), *pq2=sym(g_pq2);
    float *mr=sym(g_mrelu), *gi=sym(g_gi), *gh=sym(g_gh), *S=sym(g_S);
    unsigned short *W1h=symu(g_W1h), *W1l=symu(g_W1l);
    unsigned short *W2h=symu(g_W2h), *W2l=symu(g_W2l);
    unsigned short *W3h=symu(g_W3h), *W3l=symu(g_W3l);
    unsigned short *Wihh=symu(g_Wihh), *Wihl=symu(g_Wihl);
    unsigned short *Whhh=symu(g_Whhh), *Whhl=symu(g_Whhl);
    unsigned short *bTh=symu(g_bTh), *bTl=symu(g_bTl);

    cudaFuncSetAttribute(hgemm, cudaFuncAttributeMaxDynamicSharedMemorySize, H_SMEM);
    cudaFuncSetAttribute(big_msg_kernel, cudaFuncAttributeMaxDynamicSharedMemorySize, BIG_SMEM);
    cudaFuncSetAttribute(w4fuse_kernel, cudaFuncAttributeMaxDynamicSharedMemorySize, W4_SMEM);

    init_kernel<<<2048,256>>>(W1, W2, W3, W_ih, W_hh);
    ssum_kernel<<<Eg*128/256,256>>>(ei, node);

    hgemm<<<dim3(2,128,1),256,H_SMEM>>>(edge, W1h, W1l, x1, nullptr, Eg, 256, 16,
        0, nullptr,nullptr,nullptr,nullptr, 0.f, 1, ps1, pq1,
        nullptr,nullptr,nullptr,nullptr,nullptr);
    hgemm<<<dim3(2,128,1),256,H_SMEM>>>(x1, W2h, W2l, x2, nullptr, Eg, 256, 256,
        1, ps1, pq1, g1, b1, 1.f/Eg, 1, ps2, pq2,
        nullptr,nullptr,nullptr,nullptr,nullptr);
    hgemm<<<dim3(1,128,1),256,H_SMEM>>>(x2, W3h, W3l, x3, nullptr, Eg, 128, 256,
        1, ps2, pq2, g2, b2, 1.f/Eg, 1, sym(g_ps3), sym(g_pq3),
        nullptr,nullptr,nullptr,nullptr,nullptr);

    syrk_x3<<<dim3(16,32),256>>>(g3, b3);
    csplit_kernel<<<64,256>>>();
    w4fuse_kernel<<<128,256,W4_SMEM>>>(W4, g4, b4);

    big_msg_kernel<<<128,256,BIG_SMEM>>>(node, ei, g3, b3);

    hgemm<<<dim3(1,32,1),256,H_SMEM>>>(S, bTh, bTl, mr, bias, Ng, 128, 128,
        0, nullptr,nullptr,nullptr,nullptr, 0.f, 2, nullptr, nullptr,
        nullptr,nullptr,nullptr,nullptr,nullptr);

    hgemm<<<dim3(3,32,2),256,H_SMEM>>>(mr, Wihh, Wihl, gi, b_ih, Ng, 384, 128,
        0, nullptr,nullptr,nullptr,nullptr, 0.f, 0, nullptr, nullptr,
        hidden, Whhh, Whhl, gh, b_hh);

    int twice = (out_size >= 2*Ng*Dg) ? 1 : 0;
    gru_kernel<<<2048,256>>>(hidden, (float*)d_out, twice);
}

// round 17
// speedup vs baseline: 1.0054x; 1.0054x over previous
#include <cuda_runtime.h>
#include <cuda_bf16.h>
#include <cuda_fp16.h>
#include <cstdint>

#define Eg 16384
#define Ng 4096
#define Dg 128
#define DD 16384

static __device__ float g_x1[Eg*256];
static __device__ float g_x2[Eg*256];
static __device__ float g_x3[Eg*Dg];          // RAW (pre-BN) layer-3 output
static __device__ float g_C3[Dg*Dg];
static __device__ float g_ps1[256], g_pq1[256];
static __device__ float g_ps2[256], g_pq2[256];
static __device__ float g_ps3[128], g_pq3[128];
static __device__ float g_mx3sum[128];
static __device__ float g_msgsum[Ng*Dg];
static __device__ float g_S[Ng*Dg];
static __device__ float g_cnt[Ng];
static __device__ float g_mrelu[Ng*Dg];
static __device__ float g_gi[Ng*384];
static __device__ float g_gh[Ng*384];
static __device__ unsigned short g_Gh[DD*128];
static __device__ unsigned short g_W1h[4096],   g_W1l[4096];
static __device__ unsigned short g_W2h[65536],  g_W2l[65536];
static __device__ unsigned short g_W3h[32768],  g_W3l[32768];
static __device__ unsigned short g_Wihh[49152], g_Wihl[49152];
static __device__ unsigned short g_Whhh[49152], g_Whhl[49152];
static __device__ unsigned short g_bTh[16384],  g_bTl[16384];

// ---------- helpers ----------
__device__ __forceinline__ uint32_t smem_u32(const void* p) {
    uint32_t a;
    asm("{ .reg .u64 t; cvta.to.shared.u64 t, %1; cvt.u32.u64 %0, t; }" : "=r"(a) : "l"(p));
    return a;
}
__device__ __forceinline__ void mma_bf16(float* d, const uint32_t* a, const uint32_t* b, const float* c) {
    asm volatile("mma.sync.aligned.m16n8k16.row.col.f32.bf16.bf16.f32 "
        "{%0,%1,%2,%3}, {%4,%5,%6,%7}, {%8,%9}, {%10,%11,%12,%13};"
        : "=f"(d[0]),"=f"(d[1]),"=f"(d[2]),"=f"(d[3])
        : "r"(a[0]),"r"(a[1]),"r"(a[2]),"r"(a[3]), "r"(b[0]),"r"(b[1]),
          "f"(c[0]),"f"(c[1]),"f"(c[2]),"f"(c[3]));
}
__device__ __forceinline__ void mma_f16(float* d, const uint32_t* a, const uint32_t* b, const float* c) {
    asm volatile("mma.sync.aligned.m16n8k16.row.col.f32.f16.f16.f32 "
        "{%0,%1,%2,%3}, {%4,%5,%6,%7}, {%8,%9}, {%10,%11,%12,%13};"
        : "=f"(d[0]),"=f"(d[1]),"=f"(d[2]),"=f"(d[3])
        : "r"(a[0]),"r"(a[1]),"r"(a[2]),"r"(a[3]), "r"(b[0]),"r"(b[1]),
          "f"(c[0]),"f"(c[1]),"f"(c[2]),"f"(c[3]));
}
__device__ __forceinline__ void ldsm4(uint32_t* r, uint32_t addr) {
    asm volatile("ldmatrix.sync.aligned.m8n8.x4.shared.b16 {%0,%1,%2,%3}, [%4];"
        : "=r"(r[0]),"=r"(r[1]),"=r"(r[2]),"=r"(r[3]) : "r"(addr));
}
__device__ __forceinline__ void cp16(uint32_t dst, const void* src) {
    asm volatile("cp.async.cg.shared.global [%0], [%1], 16;" :: "r"(dst), "l"(src));
}
#define CP_COMMIT() asm volatile("cp.async.commit_group;" ::: "memory")
__device__ __forceinline__ uint32_t f2h2(float2 p) {
    __half2 h = __float22half2_rn(p);
    return *(uint32_t*)&h;
}
__device__ __forceinline__ void split2(float2 p, uint32_t& hi, uint32_t& lo) {
    uint32_t u0=__float_as_uint(p.x), u1=__float_as_uint(p.y);
    hi = __byte_perm(u0,u1,0x7632);
    float h0=__uint_as_float(u0&0xFFFF0000u), h1=__uint_as_float(u1&0xFFFF0000u);
    __nv_bfloat162 l2=__floats2bfloat162_rn(p.x-h0,p.y-h1);
    lo = *(uint32_t*)&l2;
}

// ---------- fused init ----------
__global__ void init_kernel(const float* W1, const float* W2, const float* W3,
                            const float* Wih, const float* Whh)
{
    int i = blockIdx.x*256 + threadIdx.x;
    if (i < Ng*Dg) { g_msgsum[i]=0.f; g_S[i]=0.f; }
    if (i < Ng)    g_cnt[i]=0.f;
    if (i < Dg*Dg) g_C3[i]=0.f;
    if (i < 256)   { g_ps1[i]=0.f; g_pq1[i]=0.f; g_ps2[i]=0.f; g_pq2[i]=0.f; }
    if (i < 128)   { g_ps3[i]=0.f; g_pq3[i]=0.f; g_mx3sum[i]=0.f; }
    if (i < 200704) {
        const float* src; unsigned short *dh, *dl; int off;
        if (i < 4096)        { src=W1;  dh=g_W1h;  dl=g_W1l;  off=i; }
        else if (i < 69632)  { src=W2;  dh=g_W2h;  dl=g_W2l;  off=i-4096; }
        else if (i < 102400) { src=W3;  dh=g_W3h;  dl=g_W3l;  off=i-69632; }
        else if (i < 151552) { src=Wih; dh=g_Wihh; dl=g_Wihl; off=i-102400; }
        else                 { src=Whh; dh=g_Whhh; dl=g_Whhl; off=i-151552; }
        float v = src[off];
        uint32_t u = __float_as_uint(v);
        dh[off] = (unsigned short)(u>>16);
        __nv_bfloat16 lb = __float2bfloat16_rn(v - __uint_as_float(u & 0xFFFF0000u));
        dl[off] = *(unsigned short*)&lb;
    }
}
__global__ void ssum_kernel(const int* __restrict__ ei, const float* __restrict__ node)
{
    int idx = blockIdx.x*256 + threadIdx.x;
    if (idx >= Eg*128) return;
    int e = idx>>7, k = idx&127;
    int dst = ei[2*e+1];
    atomicAdd(&g_S[(size_t)dst*128 + k], node[(size_t)ei[2*e]*128 + k]);
    if (k == 0) atomicAdd(&g_cnt[dst], 1.0f);
}

// ---------- unified tensor-core GEMM (cooperative A conversion) ----------
#define SA_OFF(s)  ((s)*10240)
#define SBH_OFF(s) (20480 + (s)*12288)
#define SBL_OFF(s) (20480 + (s)*12288 + 6144)
#define SAH_OFF(s) (45056 + (s)*12288)
#define SAL_OFF(s) (45056 + (s)*12288 + 6144)
#define SSC_OFF    69632
#define SSH_OFF    70656
#define H_SMEM     71680

__global__ __launch_bounds__(256) void hgemm(
    const float* A,
    const unsigned short* Bh, const unsigned short* Bl,
    float* C, const float* bias,
    int M, int Nc, int K,
    int amode, const float* __restrict__ psA, const float* __restrict__ pqA,
    const float* __restrict__ gA, const float* __restrict__ bA, float invE,
    int emode, float* __restrict__ psO, float* __restrict__ pqO,
    const float* A2, const unsigned short* Bh2, const unsigned short* Bl2,
    float* C2, const float* bias2)
{
    if (blockIdx.z) { A=A2; Bh=Bh2; Bl=Bl2; C=C2; bias=bias2; }
    extern __shared__ char sm[];
    uint32_t smb = smem_u32(sm);
    float* sScale = (float*)(sm + SSC_OFF);
    float* sShift = (float*)(sm + SSH_OFF);
    int tid = threadIdx.x, l = tid&31, wid = tid>>5;
    int m0 = blockIdx.y*128, n0 = blockIdx.x*128;
    int wm = (wid>>1)*32, wn = (wid&1)*64;
    int r = l>>2, c2 = (l&3)*2;
    int ln = ((l>>4)&1)*8 + (l&7);
    int colsel = (l>>3)&1;
    uint32_t aoff = (uint32_t)((l&7) + ((l>>3)&1)*8)*48 + ((l>>4)&1)*16;

    if (amode) {
        for (int c = tid; c < K; c += 256) {
            float m = psA[c]*invE;
            float var = pqA[c]*invE - m*m;
            float sc = rsqrtf(var + 1e-5f) * gA[c];
            sScale[c] = sc;
            sShift[c] = bA[c] - m*sc;
        }
    }

    float acc[2][8][4];
    #pragma unroll
    for (int mf=0;mf<2;++mf)
        #pragma unroll
        for (int nf=0;nf<8;++nf) { acc[mf][nf][0]=0;acc[mf][nf][1]=0;acc[mf][nf][2]=0;acc[mf][nf][3]=0; }

    int steps = K>>4;
    {
        #pragma unroll
        for (int i=0;i<2;++i) {
            int q = tid + i*256, row = q>>2, c4 = q&3;
            cp16(smb + SA_OFF(0) + row*80 + c4*16, A + (size_t)(m0+row)*K + c4*4);
        }
        int row = tid>>1, c = tid&1;
        cp16(smb + SBH_OFF(0) + row*48 + c*16, Bh + (size_t)(n0+row)*K + c*8);
        cp16(smb + SBL_OFF(0) + row*48 + c*16, Bl + (size_t)(n0+row)*K + c*8);
        CP_COMMIT();
    }

    for (int s=0; s<steps; ++s) {
        if (s+1 < steps) {
            int b = (s+1)&1, k0 = (s+1)*16;
            #pragma unroll
            for (int i=0;i<2;++i) {
                int q = tid + i*256, row = q>>2, c4 = q&3;
                cp16(smb + SA_OFF(b) + row*80 + c4*16, A + (size_t)(m0+row)*K + k0 + c4*4);
            }
            int row = tid>>1, c = tid&1;
            cp16(smb + SBH_OFF(b) + row*48 + c*16, Bh + (size_t)(n0+row)*K + k0 + c*8);
            cp16(smb + SBL_OFF(b) + row*48 + c*16, Bl + (size_t)(n0+row)*K + k0 + c*8);
            CP_COMMIT();
            asm volatile("cp.async.wait_group 1;" ::: "memory");
        } else {
            asm volatile("cp.async.wait_group 0;" ::: "memory");
        }
        __syncthreads();

        int k0 = s*16;
        {
            int row = tid>>1, hf = tid&1;
            const float* ar = (const float*)(sm + SA_OFF(s&1)) + row*20 + hf*8;
            float2 p[4];
            p[0]=*(const float2*)&ar[0]; p[1]=*(const float2*)&ar[2];
            p[2]=*(const float2*)&ar[4]; p[3]=*(const float2*)&ar[6];
            if (amode) {
                int cb = k0 + hf*8;
                #pragma unroll
                for (int q=0;q<4;++q) {
                    p[q].x = fmaxf(p[q].x*sScale[cb+2*q]   + sShift[cb+2*q],   0.f);
                    p[q].y = fmaxf(p[q].y*sScale[cb+2*q+1] + sShift[cb+2*q+1], 0.f);
                }
            }
            uint32_t hi[4], lo[4];
            #pragma unroll
            for (int q=0;q<4;++q) split2(p[q], hi[q], lo[q]);
            *(uint4*)(sm + SAH_OFF(s&1) + row*48 + hf*16) = make_uint4(hi[0],hi[1],hi[2],hi[3]);
            *(uint4*)(sm + SAL_OFF(s&1) + row*48 + hf*16) = make_uint4(lo[0],lo[1],lo[2],lo[3]);
        }
        __syncthreads();

        uint32_t Ah[2][4], Al[2][4];
        #pragma unroll
        for (int mf=0;mf<2;++mf) {
            ldsm4(Ah[mf], smb + SAH_OFF(s&1) + (uint32_t)(wm+mf*16)*48 + aoff);
            ldsm4(Al[mf], smb + SAL_OFF(s&1) + (uint32_t)(wm+mf*16)*48 + aoff);
        }
        uint32_t bh4[4][4], bl4[4][4];
        #pragma unroll
        for (int i=0;i<4;++i) {
            uint32_t boff = (uint32_t)(wn + 16*i + ln)*48 + colsel*16;
            ldsm4(bh4[i], smb + SBH_OFF(s&1) + boff);
            ldsm4(bl4[i], smb + SBL_OFF(s&1) + boff);
        }

        #pragma unroll
        for (int mf=0;mf<2;++mf)
            #pragma unroll
            for (int nf=0;nf<8;++nf) {
                const uint32_t* bh = &bh4[nf>>1][(nf&1)*2];
                const uint32_t* bl = &bl4[nf>>1][(nf&1)*2];
                mma_bf16(acc[mf][nf], Ah[mf], bh, acc[mf][nf]);
                mma_bf16(acc[mf][nf], Al[mf], bh, acc[mf][nf]);
                mma_bf16(acc[mf][nf], Ah[mf], bl, acc[mf][nf]);
            }
    }

    if (emode == 2) {
        #pragma unroll
        for (int mf=0;mf<2;++mf) {
            int row0 = m0+wm+mf*16+r;
            float cn0 = fmaxf(g_cnt[row0],1.f), cn1 = fmaxf(g_cnt[row0+8],1.f);
            #pragma unroll
            for (int nf=0;nf<8;++nf) {
                int col = n0+wn+nf*8+c2;
                float2 bv = *(const float2*)&bias[col];
                float2 m0v = *(const float2*)&g_msgsum[(size_t)row0*Nc + col];
                float2 m1v = *(const float2*)&g_msgsum[(size_t)(row0+8)*Nc + col];
                float2 o0, o1;
                o0.x = fmaxf((acc[mf][nf][0]+m0v.x)/cn0 + bv.x, 0.f);
                o0.y = fmaxf((acc[mf][nf][1]+m0v.y)/cn0 + bv.y, 0.f);
                o1.x = fmaxf((acc[mf][nf][2]+m1v.x)/cn1 + bv.x, 0.f);
                o1.y = fmaxf((acc[mf][nf][3]+m1v.y)/cn1 + bv.y, 0.f);
                *(float2*)&C[(size_t)row0*Nc + col]     = o0;
                *(float2*)&C[(size_t)(row0+8)*Nc + col] = o1;
            }
        }
        return;
    }
    #pragma unroll
    for (int mf=0;mf<2;++mf) {
        int row0 = m0+wm+mf*16+r;
        #pragma unroll
        for (int nf=0;nf<8;++nf) {
            int col = n0+wn+nf*8+c2;
            float2 o0 = make_float2(acc[mf][nf][0], acc[mf][nf][1]);
            float2 o1 = make_float2(acc[mf][nf][2], acc[mf][nf][3]);
            if (bias) {
                float2 bv = *(const float2*)&bias[col];
                o0.x+=bv.x; o0.y+=bv.y; o1.x+=bv.x; o1.y+=bv.y;
            }
            *(float2*)&C[(size_t)row0*Nc + col]     = o0;
            *(float2*)&C[(size_t)(row0+8)*Nc + col] = o1;
        }
    }
    if (emode == 1) {
        #pragma unroll
        for (int nf=0;nf<8;++nf) {
            float s0=0,s1=0,q0=0,q1=0;
            #pragma unroll
            for (int mf=0;mf<2;++mf) {
                float a0=acc[mf][nf][0], a1=acc[mf][nf][1], a2=acc[mf][nf][2], a3=acc[mf][nf][3];
                s0+=a0+a2; s1+=a1+a3; q0+=a0*a0+a2*a2; q1+=a1*a1+a3*a3;
            }
            #pragma unroll
            for (int st=4; st<32; st<<=1) {
                s0 += __shfl_xor_sync(0xFFFFFFFF, s0, st);
                s1 += __shfl_xor_sync(0xFFFFFFFF, s1, st);
                q0 += __shfl_xor_sync(0xFFFFFFFF, q0, st);
                q1 += __shfl_xor_sync(0xFFFFFFFF, q1, st);
            }
            if (l < 4) {
                int col = n0+wn+nf*8+c2;
                atomicAdd(&psO[col], s0);   atomicAdd(&psO[col+1], s1);
                atomicAdd(&pqO[col], q0);   atomicAdd(&pqO[col+1], q1);
            }
        }
    }
}

// ---------- fused W4 stage: C3 split in-kernel, U/q/ms/alpha/betaT/Gh in one pass ----------
#define W4A(s)   ((s)*10240)
#define W4BH     20480
#define W4BL     (20480+34816)
#define W4STASH  (20480+2*34816)
#define W4_SMEM  (W4STASH + 128*132*4)

__global__ __launch_bounds__(256,1) void w4fuse_kernel(
    const float* __restrict__ W4, const float* __restrict__ g4, const float* __restrict__ b4)
{
    extern __shared__ char sm[];
    uint32_t smb = smem_u32(sm);
    float* stash = (float*)(sm + W4STASH);
    __shared__ float sQ[128][2], sMs[128][2], sAlpha[128], sMx[128];
    int tid = threadIdx.x, l = tid&31, wid = tid>>5;
    int m0 = blockIdx.x*128;
    int wm = (wid>>1)*32, wn = (wid&1)*64;
    int r = l>>2, c2 = (l&3)*2;
    int ln = ((l>>4)&1)*8 + (l&7);
    int colsel = (l>>3)&1;

    if (tid < 128) sMx[tid] = g_mx3sum[tid];

    // stage fp32 C3 via stash temp (group 1), then A step 0 (group 2)
    {
        #pragma unroll
        for (int i=0;i<16;++i) {
            int q = tid + i*256;                 // 0..4095 quads
            cp16(smb + W4STASH + q*16, g_C3 + q*4);
        }
        CP_COMMIT();
        #pragma unroll
        for (int i=0;i<2;++i) {
            int q = tid + i*256, row = q>>2, c4 = q&3;
            cp16(smb + W4A(0) + row*80 + c4*16, W4 + (size_t)(m0+row)*128 + c4*4);
        }
        CP_COMMIT();
        asm volatile("cp.async.wait_group 1;" ::: "memory");   // C3 arrived
        __syncthreads();
        // split fp32 C3 -> bf16 hi/lo planes in SMEM
        const float* c3t = (const float*)(sm + W4STASH);
        #pragma unroll
        for (int i=0;i<8;++i) {
            int q = tid + i*256;                 // 0..2047, 8 elems each
            int base = q*8;
            int row = base>>7, col = base&127;
            float2 p0 = *(const float2*)&c3t[base+0];
            float2 p1 = *(const float2*)&c3t[base+2];
            float2 p2 = *(const float2*)&c3t[base+4];
            float2 p3 = *(const float2*)&c3t[base+6];
            uint32_t h0,l0,h1,l1,h2,l2,h3,l3;
            split2(p0,h0,l0); split2(p1,h1,l1); split2(p2,h2,l2); split2(p3,h3,l3);
            *(uint4*)(sm + W4BH + row*272 + col*2) = make_uint4(h0,h1,h2,h3);
            *(uint4*)(sm + W4BL + row*272 + col*2) = make_uint4(l0,l1,l2,l3);
        }
        __syncthreads();
    }

    float acc[2][8][4];
    #pragma unroll
    for (int mf=0;mf<2;++mf)
        #pragma unroll
        for (int nf=0;nf<8;++nf) { acc[mf][nf][0]=0;acc[mf][nf][1]=0;acc[mf][nf][2]=0;acc[mf][nf][3]=0; }

    for (int s=0; s<8; ++s) {
        if (s+1 < 8) {
            int b = (s+1)&1, k0 = (s+1)*16;
            #pragma unroll
            for (int i=0;i<2;++i) {
                int q = tid + i*256, row = q>>2, c4 = q&3;
                cp16(smb + W4A(b) + row*80 + c4*16, W4 + (size_t)(m0+row)*128 + k0 + c4*4);
            }
            CP_COMMIT();
            asm volatile("cp.async.wait_group 1;" ::: "memory");
        } else {
            asm volatile("cp.async.wait_group 0;" ::: "memory");
        }
        __syncthreads();

        #pragma unroll
        for (int i=0;i<2;++i) {
            int q = tid + i*256, row = q>>2, c4 = q&3;
            float4 v = *(const float4*)(sm + W4A(s&1) + row*80 + c4*16);
            *(float4*)&stash[row*132 + s*16 + c4*4] = v;
        }

        const float* a_ = (const float*)(sm + W4A(s&1));
        uint32_t Ah[2][4], Al[2][4];
        #pragma unroll
        for (int mf=0;mf<2;++mf) {
            const float* r0 = a_ + (wm+mf*16+r)*20;
            const float* r1 = a_ + (wm+mf*16+r+8)*20;
            float2 p[4];
            p[0]=*(const float2*)&r0[c2];   p[1]=*(const float2*)&r1[c2];
            p[2]=*(const float2*)&r0[c2+8]; p[3]=*(const float2*)&r1[c2+8];
            #pragma unroll
            for (int q=0;q<4;++q) split2(p[q], Ah[mf][q], Al[mf][q]);
        }
        uint32_t bh4[4][4], bl4[4][4];
        #pragma unroll
        for (int i=0;i<4;++i) {
            uint32_t boff = (uint32_t)(wn + 16*i + ln)*272 + s*32 + colsel*16;
            ldsm4(bh4[i], smb + W4BH + boff);
            ldsm4(bl4[i], smb + W4BL + boff);
        }
        __syncthreads();

        #pragma unroll
        for (int mf=0;mf<2;++mf)
            #pragma unroll
            for (int nf=0;nf<8;++nf) {
                const uint32_t* bh = &bh4[nf>>1][(nf&1)*2];
                const uint32_t* bl = &bl4[nf>>1][(nf&1)*2];
                mma_bf16(acc[mf][nf], Ah[mf], bh, acc[mf][nf]);
                mma_bf16(acc[mf][nf], Al[mf], bh, acc[mf][nf]);
                mma_bf16(acc[mf][nf], Ah[mf], bl, acc[mf][nf]);
            }
    }

    float qv[2][2]={{0,0},{0,0}}, mv[2][2]={{0,0},{0,0}};
    #pragma unroll
    for (int mf=0;mf<2;++mf) {
        int r0 = wm+mf*16+r;
        #pragma unroll
        for (int nf=0;nf<8;++nf) {
            int col = wn+nf*8+c2;
            float2 w0 = *(const float2*)&stash[r0*132 + col];
            float2 w1 = *(const float2*)&stash[(r0+8)*132 + col];
            float mx0 = sMx[col], mx1 = sMx[col+1];
            qv[mf][0] += acc[mf][nf][0]*w0.x + acc[mf][nf][1]*w0.y;
            mv[mf][0] += w0.x*mx0 + w0.y*mx1;
            qv[mf][1] += acc[mf][nf][2]*w1.x + acc[mf][nf][3]*w1.y;
            mv[mf][1] += w1.x*mx0 + w1.y*mx1;
        }
    }
    #pragma unroll
    for (int mf=0;mf<2;++mf)
        #pragma unroll
        for (int h=0;h<2;++h) {
            float q = qv[mf][h], m = mv[mf][h];
            q += __shfl_xor_sync(0xFFFFFFFF, q, 1);
            q += __shfl_xor_sync(0xFFFFFFFF, q, 2);
            m += __shfl_xor_sync(0xFFFFFFFF, m, 1);
            m += __shfl_xor_sync(0xFFFFFFFF, m, 2);
            if ((l&3) == 0) {
                int row = wm+mf*16+r+h*8;
                sQ[row][wid&1]  = q;
                sMs[row][wid&1] = m;
            }
        }
    __syncthreads();
    if (tid < 128) {
        float q  = sQ[tid][0]  + sQ[tid][1];
        float ms = sMs[tid][0] + sMs[tid][1];
        int c = m0 + tid;
        float m4 = ms*(1.f/Eg);
        float var = q*(1.f/Eg) - m4*m4;
        float a = g4[c]*rsqrtf(var + 1e-5f);
        sAlpha[tid] = a;
        float bv = b4[c] - m4*a;
        int t = (c&127)*128 + (c>>7);
        uint32_t uu = __float_as_uint(bv);
        g_bTh[t] = (unsigned short)(uu>>16);
        __nv_bfloat16 lb = __float2bfloat16_rn(bv - __uint_as_float(uu & 0xFFFF0000u));
        g_bTl[t] = *(unsigned short*)&lb;
    }
    __syncthreads();
    {
        int row = tid>>1, hf = tid&1;
        float a = sAlpha[row];
        unsigned short* dst = g_Gh + (size_t)(m0+row)*128 + hf*64;
        const float* src = &stash[row*132 + hf*64];
        #pragma unroll
        for (int i=0;i<8;++i) {
            float2 p0 = *(const float2*)&src[i*8+0];
            float2 p1 = *(const float2*)&src[i*8+2];
            float2 p2 = *(const float2*)&src[i*8+4];
            float2 p3 = *(const float2*)&src[i*8+6];
            p0.x*=a; p0.y*=a; p1.x*=a; p1.y*=a;
            p2.x*=a; p2.y*=a; p3.x*=a; p3.y*=a;
            uint4 o;
            o.x = f2h2(p0); o.y = f2h2(p1); o.z = f2h2(p2); o.w = f2h2(p3);
            *(uint4*)(dst + i*8) = o;
        }
    }
}

// ---------- SYRK on BN'd x3 + column sums ----------
__global__ __launch_bounds__(256) void syrk_x3(const float* __restrict__ g3,
                                               const float* __restrict__ b3)
{
    __shared__ float sAcc[8][1024];
    __shared__ float sSc[128], sSh[128];
    int tid = threadIdx.x, lane = tid&31, w = tid>>5;
    if (tid < 128) {
        float m = g_ps3[tid]*(1.f/Eg);
        float var = g_pq3[tid]*(1.f/Eg) - m*m;
        float sc = rsqrtf(var+1e-5f)*g3[tid];
        sSc[tid] = sc;
        sSh[tid] = b3[tid] - m*sc;
    }
    __syncthreads();
    int i0 = blockIdx.x*8;
    int seg = Eg/gridDim.y, e0 = blockIdx.y*seg, e1 = e0+seg;
    float acc[8][4];
    #pragma unroll
    for (int a=0;a<8;++a){acc[a][0]=0;acc[a][1]=0;acc[a][2]=0;acc[a][3]=0;}
    float csum[4]={0,0,0,0};
    float scv[4], shv[4], sci[8], shi[8];
    #pragma unroll
    for (int b=0;b<4;++b){ scv[b]=sSc[lane*4+b]; shv[b]=sSh[lane*4+b]; }
    #pragma unroll
    for (int a=0;a<8;++a){ sci[a]=sSc[i0+a]; shi[a]=sSh[i0+a]; }
    bool do_csum = (blockIdx.x == 0);

    for (int e=e0+w; e<e1; e+=8) {
        const float* row = g_x3 + (size_t)e*128;
        float4 xj = *(const float4*)&row[lane*4];
        float4 x0 = *(const float4*)&row[i0];
        float4 x1 = *(const float4*)&row[i0+4];
        float xr[8]={x0.x,x0.y,x0.z,x0.w,x1.x,x1.y,x1.z,x1.w};
        float xi[8], xv[4];
        xv[0]=fmaxf(xj.x*scv[0]+shv[0],0.f); xv[1]=fmaxf(xj.y*scv[1]+shv[1],0.f);
        xv[2]=fmaxf(xj.z*scv[2]+shv[2],0.f); xv[3]=fmaxf(xj.w*scv[3]+shv[3],0.f);
        #pragma unroll
        for (int a=0;a<8;++a) xi[a]=fmaxf(xr[a]*sci[a]+shi[a],0.f);
        if (do_csum) { csum[0]+=xv[0]; csum[1]+=xv[1]; csum[2]+=xv[2]; csum[3]+=xv[3]; }
        #pragma unroll
        for (int a=0;a<8;++a)
            #pragma unroll
            for (int b=0;b<4;++b) acc[a][b]+=xi[a]*xv[b];
    }
    #pragma unroll
    for (int a=0;a<8;++a)
        *(float4*)&sAcc[w][a*128+lane*4]=make_float4(acc[a][0],acc[a][1],acc[a][2],acc[a][3]);
    __syncthreads();
    for (int o=tid;o<1024;o+=256) {
        float s=0.f;
        #pragma unroll
        for (int ww=0;ww<8;++ww) s+=sAcc[ww][o];
        atomicAdd(&g_C3[(i0+(o>>7))*128 + (o&127)], s);
    }
    if (do_csum) {
        #pragma unroll
        for (int b=0;b<4;++b) atomicAdd(&g_mx3sum[lane*4+b], csum[b]);
    }
}

// ---------- big fused GEMM: 128-edge tiles, e×k warp split, 4-buf 3-deep pipeline ----------
#define ROWB   272
#define BUF_SIZE  (128*ROWB)
#define XIT_OFF   (4*BUF_SIZE)
#define BIG_SMEM  (XIT_OFF + 65536)

__device__ __forceinline__ void load_G(int d, int tid, uint32_t smem_base) {
    const char* GH = (const char*)g_Gh;
    uint32_t bufb = smem_base + (d&3)*BUF_SIZE;
    #pragma unroll
    for (int i=0;i<8;++i) {
        int q = tid + i*256;
        int row = q>>4, c16 = q&15;
        cp16(bufb + row*ROWB + c16*16, GH + ((size_t)d*128 + row)*256 + c16*16);
    }
    CP_COMMIT();
}

__global__ __launch_bounds__(256,1) void big_msg_kernel(
    const float* __restrict__ node, const int* __restrict__ ei,
    const float* __restrict__ g3, const float* __restrict__ b3)
{
    extern __shared__ char sm[];
    float* xiT = (float*)(sm + XIT_OFF);
    __shared__ int sDst[128];
    __shared__ float sSc3[128], sSh3[128];
    int tid = threadIdx.x, l = tid&31, w = tid>>5;
    int e0 = blockIdx.x*128;
    if (tid < 128) {
        float m = g_ps3[tid]*(1.f/Eg);
        float var = g_pq3[tid]*(1.f/Eg) - m*m;
        float sc = rsqrtf(var+1e-5f)*g3[tid];
        sSc3[tid] = sc;
        sSh3[tid] = b3[tid] - m*sc;
    }
    {
        int e = tid>>1, hf = tid&1;
        int src = ei[2*(e0+e)];
        if (hf==0) sDst[e] = ei[2*(e0+e)+1];
        const float* nr = node + (size_t)src*128 + hf*64;
        #pragma unroll
        for (int i=0;i<16;++i) {
            float4 v = *(const float4*)&nr[i*4];
            int d = hf*64 + i*4;
            xiT[(d+0)*128+e]=v.x; xiT[(d+1)*128+e]=v.y; xiT[(d+2)*128+e]=v.z; xiT[(d+3)*128+e]=v.w;
        }
    }
    float* sx3 = (float*)sm;
    {
        const float* xr = g_x3 + (size_t)e0*128;
        #pragma unroll
        for (int i=0;i<16;++i) {
            int u = tid + i*256;
            *(float4*)&sx3[u*4] = *(const float4*)&xr[u*4];
        }
    }
    __syncthreads();

    int ew = (w&3)*32, kh = w>>2;
    int r = l>>2, cq = (l&3)*2;
    uint32_t Af[8][2][4];
    {
        #pragma unroll
        for (int mf=0;mf<2;++mf) {
            const float* Xr0 = sx3 + (size_t)(ew + mf*16 + r)*128;
            const float* Xr1 = sx3 + (size_t)(ew + mf*16 + r + 8)*128;
            #pragma unroll
            for (int jt=0;jt<8;++jt) {
                int c0 = jt*16 + cq;
                float sa=sSc3[c0],   ha=sSh3[c0];
                float sb=sSc3[c0+1], hb=sSh3[c0+1];
                float sc=sSc3[c0+8], hc=sSh3[c0+8];
                float sd=sSc3[c0+9], hd=sSh3[c0+9];
                float2 p0=*(const float2*)&Xr0[c0],   p1=*(const float2*)&Xr1[c0];
                float2 p2=*(const float2*)&Xr0[c0+8], p3=*(const float2*)&Xr1[c0+8];
                p0.x=fmaxf(p0.x*sa+ha,0.f); p0.y=fmaxf(p0.y*sb+hb,0.f);
                p1.x=fmaxf(p1.x*sa+ha,0.f); p1.y=fmaxf(p1.y*sb+hb,0.f);
                p2.x=fmaxf(p2.x*sc+hc,0.f); p2.y=fmaxf(p2.y*sd+hd,0.f);
                p3.x=fmaxf(p3.x*sc+hc,0.f); p3.y=fmaxf(p3.y*sd+hd,0.f);
                Af[jt][mf][0]=f2h2(p0); Af[jt][mf][1]=f2h2(p1);
                Af[jt][mf][2]=f2h2(p2); Af[jt][mf][3]=f2h2(p3);
            }
        }
    }
    __syncthreads();

    uint32_t smem_base = smem_u32(sm);
    int ln = ((l>>4)&1)*8 + (l&7);
    int colsel = (l>>3)&1;
    uint32_t laneoff = (uint32_t)(kh*64 + ln)*ROWB + colsel*16;

    float msg[2][8][4];
    #pragma unroll
    for (int mf=0;mf<2;++mf)
        #pragma unroll
        for (int nt=0;nt<8;++nt) { msg[mf][nt][0]=0;msg[mf][nt][1]=0;msg[mf][nt][2]=0;msg[mf][nt][3]=0; }

    float zr[4];
    zr[0]=0.f; zr[1]=0.f; zr[2]=0.f; zr[3]=0.f;

    load_G(0, tid, smem_base);
    load_G(1, tid, smem_base);
    load_G(2, tid, smem_base);

    float nxi00 = xiT[0*128 + ew + r];
    float nxi01 = xiT[0*128 + ew + r + 8];
    float nxi10 = xiT[0*128 + ew + 16 + r];
    float nxi11 = xiT[0*128 + ew + 16 + r + 8];

    for (int d = 0; d < 128; ++d) {
        if (d < 126)       asm volatile("cp.async.wait_group 2;" ::: "memory");
        else if (d == 126) asm volatile("cp.async.wait_group 1;" ::: "memory");
        else               asm volatile("cp.async.wait_group 0;" ::: "memory");
        __syncthreads();
        if (d <= 124) load_G(d+3, tid, smem_base);

        uint32_t aH = smem_base + (d&3)*BUF_SIZE + laneoff;
        float xi00 = nxi00, xi01 = nxi01, xi10 = nxi10, xi11 = nxi11;
        if (d < 127) {
            nxi00 = xiT[(d+1)*128 + ew + r];
            nxi01 = xiT[(d+1)*128 + ew + r + 8];
            nxi10 = xiT[(d+1)*128 + ew + 16 + r];
            nxi11 = xiT[(d+1)*128 + ew + 16 + r + 8];
        }

        #pragma unroll
        for (int ntp = 0; ntp < 4; ++ntp) {
            float v0[8], v1[8];
            uint32_t rowoff = (uint32_t)ntp*16*ROWB;
            {
                uint32_t bh[4];
                ldsm4(bh, aH + rowoff);
                mma_f16(v0,   Af[0][0], bh,   zr);
                mma_f16(v0+4, Af[0][0], bh+2, zr);
                mma_f16(v1,   Af[0][1], bh,   zr);
                mma_f16(v1+4, Af[0][1], bh+2, zr);
            }
            #pragma unroll
            for (int jt = 1; jt < 8; ++jt) {
                uint32_t bh[4];
                ldsm4(bh, aH + rowoff + jt*32);
                mma_f16(v0,   Af[jt][0], bh,   v0);
                mma_f16(v0+4, Af[jt][0], bh+2, v0+4);
                mma_f16(v1,   Af[jt][1], bh,   v1);
                mma_f16(v1+4, Af[jt][1], bh+2, v1+4);
            }
            msg[0][2*ntp  ][0] += xi00*v0[0];
            msg[0][2*ntp  ][1] += xi00*v0[1];
            msg[0][2*ntp  ][2] += xi01*v0[2];
            msg[0][2*ntp  ][3] += xi01*v0[3];
            msg[0][2*ntp+1][0] += xi00*v0[4];
            msg[0][2*ntp+1][1] += xi00*v0[5];
            msg[0][2*ntp+1][2] += xi01*v0[6];
            msg[0][2*ntp+1][3] += xi01*v0[7];
            msg[1][2*ntp  ][0] += xi10*v1[0];
            msg[1][2*ntp  ][1] += xi10*v1[1];
            msg[1][2*ntp  ][2] += xi11*v1[2];
            msg[1][2*ntp  ][3] += xi11*v1[3];
            msg[1][2*ntp+1][0] += xi10*v1[4];
            msg[1][2*ntp+1][1] += xi10*v1[5];
            msg[1][2*ntp+1][2] += xi11*v1[6];
            msg[1][2*ntp+1][3] += xi11*v1[7];
        }
    }

    #pragma unroll
    for (int mf=0;mf<2;++mf) {
        int d0 = sDst[ew + mf*16 + r], d1 = sDst[ew + mf*16 + r + 8];
        #pragma unroll
        for (int nt = 0; nt < 8; ++nt) {
            int k = kh*64 + nt*8 + cq;
            atomicAdd(&g_msgsum[(size_t)d0*128 + k],     msg[mf][nt][0]);
            atomicAdd(&g_msgsum[(size_t)d0*128 + k + 1], msg[mf][nt][1]);
            atomicAdd(&g_msgsum[(size_t)d1*128 + k],     msg[mf][nt][2]);
            atomicAdd(&g_msgsum[(size_t)d1*128 + k + 1], msg[mf][nt][3]);
        }
    }
}

__global__ void gru_kernel(const float* __restrict__ h0, float* __restrict__ out, int twice)
{
    int i = blockIdx.x*256 + threadIdx.x;
    if (i >= Ng*Dg) return;
    int n = i>>7, k = i&127;
    const float* gir = g_gi + (size_t)n*384;
    const float* ghr = g_gh + (size_t)n*384;
    float r = 1.f/(1.f + expf(-(gir[k]     + ghr[k])));
    float z = 1.f/(1.f + expf(-(gir[128+k] + ghr[128+k])));
    float nn = tanhf(gir[256+k] + r*ghr[256+k]);
    float hn = (1.f - z)*nn + z*h0[i];
    out[i] = hn;
    if (twice) out[Ng*Dg + i] = hn;
}

static float* sym(const void* s) { void* p=0; cudaGetSymbolAddress(&p, s); return (float*)p; }
static unsigned short* symu(const void* s) { void* p=0; cudaGetSymbolAddress(&p, s); return (unsigned short*)p; }

extern "C" void kernel_launch(void* const* d_in, const int* in_sizes, int n_in,
                              void* d_out, int out_size)
{
    const float* node   = (const float*)d_in[0];
    const int*   ei     = (const int*)  d_in[1];
    const float* edge   = (const float*)d_in[2];
    const float* hidden = (const float*)d_in[3];
    const float* W1=(const float*)d_in[4],  *g1=(const float*)d_in[5],  *b1=(const float*)d_in[6];
    const float* W2=(const float*)d_in[7],  *g2=(const float*)d_in[8],  *b2=(const float*)d_in[9];
    const float* W3=(const float*)d_in[10], *g3=(const float*)d_in[11], *b3=(const float*)d_in[12];
    const float* W4=(const float*)d_in[13];
    const float* g4=(const float*)d_in[14], *b4=(const float*)d_in[15];
    const float* bias=(const float*)d_in[16];
    const float* W_ih=(const float*)d_in[17], *W_hh=(const float*)d_in[18];
    const float* b_ih=(const float*)d_in[19], *b_hh=(const float*)d_in[20];
    (void)in_sizes; (void)n_in;

    float *x1=sym(g_x1), *x2=sym(g_x2), *x3=sym(g_x3);
    float *ps1=sym(g_ps1), *pq1=sym(g_pq1), *ps2=sym(g_ps2), *pq2=sym(g_pq2);
    float *mr=sym(g_mrelu), *gi=sym(g_gi), *gh=sym(g_gh), *S=sym(g_S);
    unsigned short *W1h=symu(g_W1h), *W1l=symu(g_W1l);
    unsigned short *W2h=symu(g_W2h), *W2l=symu(g_W2l);
    unsigned short *W3h=symu(g_W3h), *W3l=symu(g_W3l);
    unsigned short *Wihh=symu(g_Wihh), *Wihl=symu(g_Wihl);
    unsigned short *Whhh=symu(g_Whhh), *Whhl=symu(g_Whhl);
    unsigned short *bTh=symu(g_bTh), *bTl=symu(g_bTl);

    cudaFuncSetAttribute(hgemm, cudaFuncAttributeMaxDynamicSharedMemorySize, H_SMEM);
    cudaFuncSetAttribute(big_msg_kernel, cudaFuncAttributeMaxDynamicSharedMemorySize, BIG_SMEM);
    cudaFuncSetAttribute(w4fuse_kernel, cudaFuncAttributeMaxDynamicSharedMemorySize, W4_SMEM);

    init_kernel<<<2048,256>>>(W1, W2, W3, W_ih, W_hh);
    ssum_kernel<<<Eg*128/256,256>>>(ei, node);

    hgemm<<<dim3(2,128,1),256,H_SMEM>>>(edge, W1h, W1l, x1, nullptr, Eg, 256, 16,
        0, nullptr,nullptr,nullptr,nullptr, 0.f, 1, ps1, pq1,
        nullptr,nullptr,nullptr,nullptr,nullptr);
    hgemm<<<dim3(2,128,1),256,H_SMEM>>>(x1, W2h, W2l, x2, nullptr, Eg, 256, 256,
        1, ps1, pq1, g1, b1, 1.f/Eg, 1, ps2, pq2,
        nullptr,nullptr,nullptr,nullptr,nullptr);
    hgemm<<<dim3(1,128,1),256,H_SMEM>>>(x2, W3h, W3l, x3, nullptr, Eg, 128, 256,
        1, ps2, pq2, g2, b2, 1.f/Eg, 1, sym(g_ps3), sym(g_pq3),
        nullptr,nullptr,nullptr,nullptr,nullptr);

    syrk_x3<<<dim3(16,32),256>>>(g3, b3);
    w4fuse_kernel<<<128,256,W4_SMEM>>>(W4, g4, b4);

    big_msg_kernel<<<128,256,BIG_SMEM>>>(node, ei, g3, b3);

    hgemm<<<dim3(1,32,1),256,H_SMEM>>>(S, bTh, bTl, mr, bias, Ng, 128, 128,
        0, nullptr,nullptr,nullptr,nullptr, 0.f, 2, nullptr, nullptr,
        nullptr,nullptr,nullptr,nullptr,nullptr);

    hgemm<<<dim3(3,32,2),256,H_SMEM>>>(mr, Wihh, Wihl, gi, b_ih, Ng, 384, 128,
        0, nullptr,nullptr,nullptr,nullptr, 0.f, 0, nullptr, nullptr,
        hidden, Whhh, Whhl, gh, b_hh);

    int twice = (out_size >= 2*Ng*Dg) ? 1 : 0;
    gru_kernel<<<2048,256>>>(hidden, (float*)d_out, twice);
}